// round 10
// baseline (speedup 1.0000x reference)
#include <cuda_runtime.h>
#include <math.h>

#define B 4
#define N 512
#define HID 100
#define HP 128
#define OUTF 6
#define IT 16            // receivers per K2 block
#define JG 8             // j-groups per block
#define UJ 8             // j prefetch depth (per half of ping-pong)

typedef unsigned long long u64;

// Scratch (static device; no allocation anywhere)
__device__ float g_P[B * N * HP];
__device__ float g_Q[B * N * HP];

__device__ __forceinline__ float softplus_f(float v)
{
    return fmaxf(v, 0.f) + log1pf(expf(-fabsf(v)));
}

// packed r = a*1.0x2 + c  (double-rate fp32 path, sm_100+)
__device__ __forceinline__ u64 fma2_1(u64 a, u64 one2, u64 c)
{
    u64 r;
    asm("fma.rn.f32x2 %0, %1, %2, %3;" : "=l"(r) : "l"(a), "l"(one2), "l"(c));
    return r;
}

__device__ __forceinline__ u64 add2(u64 a, u64 b)
{
    u64 r;
    asm("add.rn.f32x2 %0, %1, %2;" : "=l"(r) : "l"(a), "l"(b));
    return r;
}

// ---------------------------------------------------------------------------
// K1: build P', Q for all (b,n,k).  Block = 128 k-lanes x 16 (b,n) rows.
// ---------------------------------------------------------------------------
__global__ __launch_bounds__(128) void k1_build_PQ(
    const float* __restrict__ inp, const float* __restrict__ W1,
    const float* __restrict__ b1)
{
    int bn0 = blockIdx.x * 16;
    int k   = threadIdx.x;

    __shared__ float rows[16][6];
    if (threadIdx.x < 96) {
        int r = threadIdx.x / 6, c = threadIdx.x % 6;
        rows[r][c] = inp[(bn0 + r) * 6 + c];
    }
    __syncthreads();

    float w0=0,w1=0,w2=0,w3=0,w4=0,w5=0,w6=0,w7=0,w8=0,w9=0,bk=0;
    if (k < HID) {
        w0 = W1[0*HID+k]; w1 = W1[1*HID+k]; w2 = W1[2*HID+k]; w3 = W1[3*HID+k];
        w4 = W1[4*HID+k]; w5 = W1[5*HID+k]; w6 = W1[6*HID+k]; w7 = W1[7*HID+k];
        w8 = W1[8*HID+k]; w9 = W1[9*HID+k]; bk = b1[k];
    }

    #pragma unroll
    for (int r = 0; r < 16; r++) {
        float y = rows[r][0], x = rows[r][1], tau = rows[r][2];
        float sig = rows[r][3], c = rows[r][4], d = rows[r][5];
        float P = 0.f, Q = 0.f;
        if (k < HID) {
            P = tau*w0 + sig*w1 + c*w2 + d*w3 + y*w8 + x*w9 + bk;
            Q = tau*w4 + sig*w5 + c*w6 + d*w7 - y*w8 - x*w9;
        }
        g_P[(bn0 + r) * HP + k] = P;
        g_Q[(bn0 + r) * HP + k] = Q;
    }
}

// ---------------------------------------------------------------------------
// K2: fused O(N^2) abs-sum + sumQ + epilogue, packed f32x2 inner loop.
// Block = 512 thr = 8 j-groups x 64 packed-k lanes; IT=16; grid=128.
// Per (j, 2 k-lanes, i): t2 = fma2(q2,1,p2); t2 &= ~signs (2x LOP3, alu);
//                        acc2 = fma2(t2,1,acc2).  fma pipe 2cyc/pair.
// ---------------------------------------------------------------------------
__global__ __launch_bounds__(512) void k2_fused(
    const float* __restrict__ inp, const float* __restrict__ W2,
    const float* __restrict__ b2, float* __restrict__ out)
{
    int b    = blockIdx.x >> 5;              // 32 tiles per batch
    int i0   = (blockIdx.x & 31) * IT;
    int tid  = threadIdx.x;
    int jg   = tid >> 6;                     // 0..7
    int lane = tid & 63;                     // packed k-pair: k = 2*lane, 2*lane+1

    const u64 ONE2  = 0x3F8000003F800000ULL;
    const u64 AMASK = 0x7FFFFFFF7FFFFFFFULL;

    const u64* P2 = (const u64*)(g_P + (b * N + i0) * HP) + lane;
    u64 p2[IT];
    #pragma unroll
    for (int ii = 0; ii < IT; ii++) p2[ii] = P2[ii * (HP / 2)];

    u64 acc2[IT];
    #pragma unroll
    for (int ii = 0; ii < IT; ii++) acc2[ii] = 0ULL;
    u64 sq2 = 0ULL;

    const int NJ = N / JG;                   // 64 j's per group
    const u64* q = (const u64*)(g_Q + (b * N + jg * NJ) * HP) + lane;

    u64 qa[UJ], qb[UJ];
    #pragma unroll
    for (int u = 0; u < UJ; u++) qa[u] = q[u * (HP / 2)];

    #pragma unroll 1
    for (int j0 = 0; j0 < NJ; j0 += 2 * UJ) {
        // prefetch strip B while computing strip A
        #pragma unroll
        for (int u = 0; u < UJ; u++) qb[u] = q[(j0 + UJ + u) * (HP / 2)];

        #pragma unroll
        for (int u = 0; u < UJ; u++) {
            u64 q2 = qa[u];
            sq2 = fma2_1(q2, ONE2, sq2);
            #pragma unroll
            for (int ii = 0; ii < IT; ii++) {
                u64 t2 = fma2_1(q2, ONE2, p2[ii]) & AMASK;
                acc2[ii] = fma2_1(t2, ONE2, acc2[ii]);
            }
        }

        // prefetch next strip A (uniform guard; no OOB)
        bool more = (j0 + 2 * UJ) < NJ;
        #pragma unroll
        for (int u = 0; u < UJ; u++)
            if (more) qa[u] = q[(j0 + 2 * UJ + u) * (HP / 2)];

        #pragma unroll
        for (int u = 0; u < UJ; u++) {
            u64 q2 = qb[u];
            sq2 = fma2_1(q2, ONE2, sq2);
            #pragma unroll
            for (int ii = 0; ii < IT; ii++) {
                u64 t2 = fma2_1(q2, ONE2, p2[ii]) & AMASK;
                acc2[ii] = fma2_1(t2, ONE2, acc2[ii]);
            }
        }
    }

    // two-round jg reduction into 4 slots (8B stores; unique addr per thread)
    __shared__ float smT[4][IT][HP];
    __shared__ float smSQ[4][HP];
    if (jg < 4) {
        #pragma unroll
        for (int ii = 0; ii < IT; ii++)
            *(u64*)&smT[jg][ii][2 * lane] = acc2[ii];
        *(u64*)&smSQ[jg][2 * lane] = sq2;
    }
    __syncthreads();
    if (jg >= 4) {
        #pragma unroll
        for (int ii = 0; ii < IT; ii++) {
            u64* d = (u64*)&smT[jg - 4][ii][2 * lane];
            *d = add2(*d, acc2[ii]);
        }
        u64* ds = (u64*)&smSQ[jg - 4][2 * lane];
        *ds = add2(*ds, sq2);
    }
    __syncthreads();

    // epilogue: warp w -> receiver i=w; lane sub -> k = sub + 32*kk
    int i   = tid >> 5;                      // 0..15
    int sub = tid & 31;
    int gi  = b * N + i0 + i;

    float par[OUTF];
    #pragma unroll
    for (int o = 0; o < OUTF; o++) par[o] = 0.f;

    #pragma unroll
    for (int kk = 0; kk < 4; kk++) {
        int kc = sub + 32 * kk;
        if (kc < HID) {
            float T = (smT[0][i][kc] + smT[1][i][kc])
                    + (smT[2][i][kc] + smT[3][i][kc]);
            float sqt = (smSQ[0][kc] + smSQ[1][kc])
                      + (smSQ[2][kc] + smSQ[3][kc]);
            float Pi = g_P[gi * HP + kc];
            float Qi = g_Q[gi * HP + kc];
            float S = 0.55f * ((float)(N - 1) * Pi + sqt - Qi)
                    + 0.45f * (T - fabsf(Pi + Qi));
            #pragma unroll
            for (int o = 0; o < OUTF; o++)
                par[o] += S * W2[kc * OUTF + o];
        }
    }
    #pragma unroll
    for (int off = 16; off > 0; off >>= 1)
        #pragma unroll
        for (int o = 0; o < OUTF; o++)
            par[o] += __shfl_down_sync(0xFFFFFFFFu, par[o], off);

    if (sub == 0) {
        const float* e = inp + gi * 6;
        float* ot = out + gi * 6;
        float p0 = par[0] + (float)(N - 1) * b2[0];
        float p1 = par[1] + (float)(N - 1) * b2[1];
        float p2e = par[2] + (float)(N - 1) * b2[2];
        float p3 = par[3] + (float)(N - 1) * b2[3];
        float p4 = par[4] + (float)(N - 1) * b2[4];
        float p5 = par[5] + (float)(N - 1) * b2[5];
        ot[0] = e[0] + 0.1f * p0;
        ot[1] = e[1] + 0.1f * p1;
        ot[2] = e[2] + 0.1f * p2e;
        ot[3] = e[3] + 0.1f * p3;
        ot[4] = 0.1f * softplus_f(p4);
        ot[5] = 0.1f * softplus_f(p5);
    }
}

// ---------------------------------------------------------------------------
extern "C" void kernel_launch(void* const* d_in, const int* in_sizes, int n_in,
                              void* d_out, int out_size)
{
    const float* inp = (const float*)d_in[0];
    const float* W1  = (const float*)d_in[1];
    const float* b1  = (const float*)d_in[2];
    const float* W2  = (const float*)d_in[3];
    const float* b2  = (const float*)d_in[4];
    float* out = (float*)d_out;

    k1_build_PQ<<<B * N / 16, 128>>>(inp, W1, b1);
    k2_fused<<<B * (N / IT), 512>>>(inp, W2, b2, out);
}

// round 11
// speedup vs baseline: 1.2148x; 1.2148x over previous
#include <cuda_runtime.h>
#include <math.h>

#define B 4
#define N 512
#define HID 100
#define HP 128
#define OUTF 6
#define IT 14            // receivers per K2 block (37 tiles x 14 >= 512)
#define NT 37            // i-tiles per batch
#define JG 8             // j-groups per block (1024 threads)
#define UJ 8             // j prefetch depth (per half of ping-pong)

// Scratch (static device; no allocation anywhere)
__device__ float g_P[B * N * HP];
__device__ float g_Q[B * N * HP];

__device__ __forceinline__ float softplus_f(float v)
{
    return fmaxf(v, 0.f) + log1pf(expf(-fabsf(v)));
}

// t = q*1.0 + p  as FFMA with immediate multiplier
__device__ __forceinline__ float fma1(float q, float p)
{
    float r;
    asm("fma.rn.f32 %0, %1, 0f3F800000, %2;" : "=f"(r) : "f"(q), "f"(p));
    return r;
}

// ---------------------------------------------------------------------------
// K1: build P', Q for all (b,n,k).  Block = 128 k-lanes x 16 (b,n) rows.
// ---------------------------------------------------------------------------
__global__ __launch_bounds__(128) void k1_build_PQ(
    const float* __restrict__ inp, const float* __restrict__ W1,
    const float* __restrict__ b1)
{
    int bn0 = blockIdx.x * 16;
    int k   = threadIdx.x;

    __shared__ float rows[16][6];
    if (threadIdx.x < 96) {
        int r = threadIdx.x / 6, c = threadIdx.x % 6;
        rows[r][c] = inp[(bn0 + r) * 6 + c];
    }
    __syncthreads();

    float w0=0,w1=0,w2=0,w3=0,w4=0,w5=0,w6=0,w7=0,w8=0,w9=0,bk=0;
    if (k < HID) {
        w0 = W1[0*HID+k]; w1 = W1[1*HID+k]; w2 = W1[2*HID+k]; w3 = W1[3*HID+k];
        w4 = W1[4*HID+k]; w5 = W1[5*HID+k]; w6 = W1[6*HID+k]; w7 = W1[7*HID+k];
        w8 = W1[8*HID+k]; w9 = W1[9*HID+k]; bk = b1[k];
    }

    #pragma unroll
    for (int r = 0; r < 16; r++) {
        float y = rows[r][0], x = rows[r][1], tau = rows[r][2];
        float sig = rows[r][3], c = rows[r][4], d = rows[r][5];
        float P = 0.f, Q = 0.f;
        if (k < HID) {
            P = tau*w0 + sig*w1 + c*w2 + d*w3 + y*w8 + x*w9 + bk;
            Q = tau*w4 + sig*w5 + c*w6 + d*w7 - y*w8 - x*w9;
        }
        g_P[(bn0 + r) * HP + k] = P;
        g_Q[(bn0 + r) * HP + k] = Q;
    }
}

// ---------------------------------------------------------------------------
// K2: fused O(N^2) abs-sum + sumQ + epilogue.
// Grid = 148 = B x 37 tiles; block = 1024 thr = 8 j-groups x 128 k-lanes.
// IT=14 receivers/tile; overhang receivers (i >= 512) run with P=0 and
// their stores are suppressed.  Scalar inner: FFMA-imm + FADD(|.|).
// ---------------------------------------------------------------------------
__global__ __launch_bounds__(1024) void k2_fused(
    const float* __restrict__ inp, const float* __restrict__ W2,
    const float* __restrict__ b2, float* __restrict__ out)
{
    int b   = blockIdx.x / NT;
    int i0  = (blockIdx.x % NT) * IT;
    int tid = threadIdx.x;
    int jg  = tid >> 7;                      // 0..7
    int k   = tid & (HP - 1);                // 0..127
    int nv  = N - i0;                        // valid receivers in this tile

    const float* Pp = g_P + (b * N + i0) * HP + k;
    float p[IT];
    #pragma unroll
    for (int ii = 0; ii < IT; ii++)
        p[ii] = (ii < nv) ? Pp[ii * HP] : 0.f;

    float acc[IT];
    #pragma unroll
    for (int ii = 0; ii < IT; ii++) acc[ii] = 0.f;
    float sq = 0.f;

    const int NJ = N / JG;                   // 64 j's per group
    const float* q = g_Q + (b * N + jg * NJ) * HP + k;

    float qa[UJ], qb[UJ];
    #pragma unroll
    for (int u = 0; u < UJ; u++) qa[u] = q[u * HP];

    #pragma unroll 1
    for (int j0 = 0; j0 < NJ; j0 += 2 * UJ) {
        // prefetch strip B while computing strip A
        #pragma unroll
        for (int u = 0; u < UJ; u++) qb[u] = q[(j0 + UJ + u) * HP];

        #pragma unroll
        for (int u = 0; u < UJ; u++) {
            float qv = qa[u];
            sq = fma1(qv, sq);
            #pragma unroll
            for (int ii = 0; ii < IT; ii++)
                acc[ii] += fabsf(fma1(qv, p[ii]));
        }

        // prefetch next strip A (uniform guard; no OOB)
        bool more = (j0 + 2 * UJ) < NJ;
        #pragma unroll
        for (int u = 0; u < UJ; u++)
            if (more) qa[u] = q[(j0 + 2 * UJ + u) * HP];

        #pragma unroll
        for (int u = 0; u < UJ; u++) {
            float qv = qb[u];
            sq = fma1(qv, sq);
            #pragma unroll
            for (int ii = 0; ii < IT; ii++)
                acc[ii] += fabsf(fma1(qv, p[ii]));
        }
    }

    // two-round jg reduction into 4 slots (race-free: unique addr per thread)
    __shared__ float smT[4][IT][HP];
    __shared__ float smSQ[4][HP];
    if (jg < 4) {
        #pragma unroll
        for (int ii = 0; ii < IT; ii++) smT[jg][ii][k] = acc[ii];
        smSQ[jg][k] = sq;
    }
    __syncthreads();
    if (jg >= 4) {
        #pragma unroll
        for (int ii = 0; ii < IT; ii++) smT[jg - 4][ii][k] += acc[ii];
        smSQ[jg - 4][k] += sq;
    }
    __syncthreads();

    // epilogue on first IT warps: warp w -> receiver i=w; lane sub -> k
    if (tid < IT * 32) {
        int i   = tid >> 5;                  // 0..IT-1
        int sub = tid & 31;
        int iglob = i0 + i;
        int gi  = b * N + (iglob < N ? iglob : N - 1);   // clamp (unused if invalid)

        float par[OUTF];
        #pragma unroll
        for (int o = 0; o < OUTF; o++) par[o] = 0.f;

        #pragma unroll
        for (int kk = 0; kk < 4; kk++) {
            int kc = sub + 32 * kk;
            if (kc < HID) {
                float T = (smT[0][i][kc] + smT[1][i][kc])
                        + (smT[2][i][kc] + smT[3][i][kc]);
                float sqt = (smSQ[0][kc] + smSQ[1][kc])
                          + (smSQ[2][kc] + smSQ[3][kc]);
                float Pi = g_P[gi * HP + kc];
                float Qi = g_Q[gi * HP + kc];
                float S = 0.55f * ((float)(N - 1) * Pi + sqt - Qi)
                        + 0.45f * (T - fabsf(Pi + Qi));
                #pragma unroll
                for (int o = 0; o < OUTF; o++)
                    par[o] += S * W2[kc * OUTF + o];
            }
        }
        #pragma unroll
        for (int off = 16; off > 0; off >>= 1)
            #pragma unroll
            for (int o = 0; o < OUTF; o++)
                par[o] += __shfl_down_sync(0xFFFFFFFFu, par[o], off);

        if (sub == 0 && iglob < N) {
            const float* e = inp + (b * N + iglob) * 6;
            float* ot = out + (b * N + iglob) * 6;
            float p0 = par[0] + (float)(N - 1) * b2[0];
            float p1 = par[1] + (float)(N - 1) * b2[1];
            float p2 = par[2] + (float)(N - 1) * b2[2];
            float p3 = par[3] + (float)(N - 1) * b2[3];
            float p4 = par[4] + (float)(N - 1) * b2[4];
            float p5 = par[5] + (float)(N - 1) * b2[5];
            ot[0] = e[0] + 0.1f * p0;
            ot[1] = e[1] + 0.1f * p1;
            ot[2] = e[2] + 0.1f * p2;
            ot[3] = e[3] + 0.1f * p3;
            ot[4] = 0.1f * softplus_f(p4);
            ot[5] = 0.1f * softplus_f(p5);
        }
    }
}

// ---------------------------------------------------------------------------
extern "C" void kernel_launch(void* const* d_in, const int* in_sizes, int n_in,
                              void* d_out, int out_size)
{
    const float* inp = (const float*)d_in[0];
    const float* W1  = (const float*)d_in[1];
    const float* b1  = (const float*)d_in[2];
    const float* W2  = (const float*)d_in[3];
    const float* b2  = (const float*)d_in[4];
    float* out = (float*)d_out;

    k1_build_PQ<<<B * N / 16, 128>>>(inp, W1, b1);
    k2_fused<<<B * NT, 1024>>>(inp, W2, b2, out);
}

// round 12
// speedup vs baseline: 1.3328x; 1.0971x over previous
#include <cuda_runtime.h>
#include <math.h>

#define B 4
#define N 512
#define HID 100
#define HP 128
#define OUTF 6

// Scratch (static device; no allocation anywhere)
__device__ float g_S[B * N * HP];

__device__ __forceinline__ float softplus_f(float v)
{
    return fmaxf(v, 0.f) + log1pf(expf(-fabsf(v)));
}

// ---------------------------------------------------------------------------
// kA: one block per (b, k) column, 512 threads (thread = node j).
// 1) stage inp[b] to smem; compute P_j[k], Q_j[k]
// 2) bitonic-sort the 512 Q values (ascending)
// 3) inclusive prefix scan of sorted Q
// 4) each thread binary-searches m = #{Qs < -P_j}; closed-form T;
//    S_j[k] via the validated epilogue formula; write to g_S.
// ---------------------------------------------------------------------------
__global__ __launch_bounds__(512) void kA(
    const float* __restrict__ inp, const float* __restrict__ W1,
    const float* __restrict__ b1)
{
    int b   = blockIdx.x / HID;
    int k   = blockIdx.x - b * HID;
    int tid = threadIdx.x;

    __shared__ float sx[N * 6];
    __shared__ float Qs[N];
    __shared__ float Ia[N], Ib[N];

    // coalesced stage of inp[b] (3072 floats)
    #pragma unroll
    for (int i = 0; i < 6; i++)
        sx[tid + i * N] = inp[b * N * 6 + tid + i * N];
    __syncthreads();

    // this thread's node features (row tid)
    float y   = sx[tid * 6 + 0];
    float x   = sx[tid * 6 + 1];
    float tau = sx[tid * 6 + 2];
    float sig = sx[tid * 6 + 3];
    float c   = sx[tid * 6 + 4];
    float d   = sx[tid * 6 + 5];

    // W1 column k (uniform across block)
    float w0 = W1[0*HID+k], w1 = W1[1*HID+k], w2 = W1[2*HID+k], w3 = W1[3*HID+k];
    float w4 = W1[4*HID+k], w5 = W1[5*HID+k], w6 = W1[6*HID+k], w7 = W1[7*HID+k];
    float w8 = W1[8*HID+k], w9 = W1[9*HID+k], bk = b1[k];

    float P = tau*w0 + sig*w1 + c*w2 + d*w3 + y*w8 + x*w9 + bk;
    float Q = tau*w4 + sig*w5 + c*w6 + d*w7 - y*w8 - x*w9;

    Qs[tid] = Q;
    __syncthreads();

    // bitonic sort, ascending
    #pragma unroll 1
    for (int size = 2; size <= N; size <<= 1) {
        #pragma unroll 1
        for (int stride = size >> 1; stride > 0; stride >>= 1) {
            int pa = tid ^ stride;
            if (pa > tid) {
                float a  = Qs[tid];
                float c2 = Qs[pa];
                bool up = ((tid & size) == 0);
                if ((a > c2) == up) { Qs[tid] = c2; Qs[pa] = a; }
            }
            __syncthreads();
        }
    }

    // inclusive scan (Hillis-Steele, ping-pong) — preserves Qs
    Ia[tid] = Qs[tid];
    __syncthreads();
    float* src = Ia;
    float* dst = Ib;
    #pragma unroll
    for (int off = 1; off < N; off <<= 1) {
        float v = src[tid];
        if (tid >= off) v += src[tid - off];
        dst[tid] = v;
        __syncthreads();
        float* t = src; src = dst; dst = t;
    }
    float SQ = src[N - 1];

    // binary search: m = count of Qs[] < -P  (ties land either side; term is 0)
    float key = -P;
    int lo = 0, hi = N;
    #pragma unroll
    for (int it = 0; it < 9; it++) {
        int mid = (lo + hi) >> 1;
        bool lt = Qs[mid] < key;
        lo = lt ? mid + 1 : lo;
        hi = lt ? hi : mid;
    }
    float Cm = (lo == 0) ? 0.f : src[lo - 1];
    float T  = (float)(N - 2 * lo) * P + SQ - 2.f * Cm;

    float S = 0.55f * ((float)(N - 1) * P + SQ - Q)
            + 0.45f * (T - fabsf(P + Q));
    g_S[(b * N + tid) * HP + k] = S;
}

// ---------------------------------------------------------------------------
// kB: epilogue.  Warp per (b,i) row: par[o] = sum_k S[row][k]*W2[k][o];
// then final combine + softplus.  Grid = B*N/8 blocks x 8 warps.
// ---------------------------------------------------------------------------
__global__ __launch_bounds__(256) void kB(
    const float* __restrict__ inp, const float* __restrict__ W2,
    const float* __restrict__ b2, float* __restrict__ out)
{
    int w    = threadIdx.x >> 5;
    int lane = threadIdx.x & 31;
    int row  = blockIdx.x * 8 + w;          // b*N + i

    const float* Sr = g_S + row * HP;

    float par[OUTF];
    #pragma unroll
    for (int o = 0; o < OUTF; o++) par[o] = 0.f;

    #pragma unroll
    for (int cc = 0; cc < 4; cc++) {
        int kc = lane + 32 * cc;
        if (kc < HID) {
            float s = Sr[kc];
            #pragma unroll
            for (int o = 0; o < OUTF; o++)
                par[o] += s * W2[kc * OUTF + o];
        }
    }
    #pragma unroll
    for (int off = 16; off > 0; off >>= 1)
        #pragma unroll
        for (int o = 0; o < OUTF; o++)
            par[o] += __shfl_down_sync(0xFFFFFFFFu, par[o], off);

    if (lane == 0) {
        const float* e = inp + row * 6;
        float* ot = out + row * 6;
        float p0 = par[0] + (float)(N - 1) * b2[0];
        float p1 = par[1] + (float)(N - 1) * b2[1];
        float p2 = par[2] + (float)(N - 1) * b2[2];
        float p3 = par[3] + (float)(N - 1) * b2[3];
        float p4 = par[4] + (float)(N - 1) * b2[4];
        float p5 = par[5] + (float)(N - 1) * b2[5];
        ot[0] = e[0] + 0.1f * p0;
        ot[1] = e[1] + 0.1f * p1;
        ot[2] = e[2] + 0.1f * p2;
        ot[3] = e[3] + 0.1f * p3;
        ot[4] = 0.1f * softplus_f(p4);
        ot[5] = 0.1f * softplus_f(p5);
    }
}

// ---------------------------------------------------------------------------
extern "C" void kernel_launch(void* const* d_in, const int* in_sizes, int n_in,
                              void* d_out, int out_size)
{
    const float* inp = (const float*)d_in[0];
    const float* W1  = (const float*)d_in[1];
    const float* b1  = (const float*)d_in[2];
    const float* W2  = (const float*)d_in[3];
    const float* b2  = (const float*)d_in[4];
    float* out = (float*)d_out;

    kA<<<B * HID, 512>>>(inp, W1, b1);
    kB<<<B * N / 8, 256>>>(inp, W2, b2, out);
}

// round 13
// speedup vs baseline: 1.7165x; 1.2879x over previous
#include <cuda_runtime.h>
#include <math.h>

#define B 4
#define N 512
#define HID 100
#define HP 128
#define OUTF 6
#define FULL 0xFFFFFFFFu

// Scratch (static device; no allocation anywhere)
__device__ float g_S[B * N * HP];

__device__ __forceinline__ float softplus_f(float v)
{
    return fmaxf(v, 0.f) + log1pf(expf(-fabsf(v)));
}

// ---------------------------------------------------------------------------
// kA: one block per (b, k) column, 512 threads (thread = node j).
// P_j, Q_j from inp row + W1 column k; hybrid bitonic sort of Q (shfl for
// stride<32, smem for stride>=32); warp-shuffle prefix scan; binary search
// -> closed-form T -> S_j[k].
// ---------------------------------------------------------------------------
__global__ __launch_bounds__(512) void kA(
    const float* __restrict__ inp, const float* __restrict__ W1,
    const float* __restrict__ b1)
{
    int b    = blockIdx.x / HID;
    int k    = blockIdx.x - b * HID;
    int tid  = threadIdx.x;
    int lane = tid & 31;
    int wid  = tid >> 5;

    __shared__ float Qs[N];      // sorted Q values
    __shared__ float Cs[N];      // inclusive prefix of sorted Q
    __shared__ float wsum[16];   // warp sums for scan
    __shared__ float xch[N];     // exchange buffer for smem sort passes

    // this thread's node features (direct LDG; L2-resident across 400 blocks)
    const float* e = inp + (b * N + tid) * 6;
    float y = e[0], x = e[1], tau = e[2], sig = e[3], c = e[4], d = e[5];

    // W1 column k (uniform across block; LDG via read-only path)
    float w0 = W1[0*HID+k], w1 = W1[1*HID+k], w2 = W1[2*HID+k], w3 = W1[3*HID+k];
    float w4 = W1[4*HID+k], w5 = W1[5*HID+k], w6 = W1[6*HID+k], w7 = W1[7*HID+k];
    float w8 = W1[8*HID+k], w9 = W1[9*HID+k], bk = b1[k];

    float P = tau*w0 + sig*w1 + c*w2 + d*w3 + y*w8 + x*w9 + bk;
    float Q = tau*w4 + sig*w5 + c*w6 + d*w7 - y*w8 - x*w9;

    // ---- bitonic sort (ascending across tid), value v lives in a register
    float v = Q;
    #pragma unroll
    for (int size = 2; size <= N; size <<= 1) {
        bool dirAsc = ((tid & size) == 0);
        #pragma unroll
        for (int stride = size >> 1; stride > 0; stride >>= 1) {
            float pv;
            if (stride >= 32) {
                xch[tid] = v;
                __syncthreads();
                pv = xch[tid ^ stride];
                __syncthreads();
            } else {
                pv = __shfl_xor_sync(FULL, v, stride);
            }
            bool lower = ((tid & stride) == 0);
            v = (lower == dirAsc) ? fminf(v, pv) : fmaxf(v, pv);
        }
    }
    // v = Qs_sorted[tid]
    Qs[tid] = v;

    // ---- inclusive scan of sorted values: warp shfl scan + warp-sum scan
    float s = v;
    #pragma unroll
    for (int off = 1; off < 32; off <<= 1) {
        float t = __shfl_up_sync(FULL, s, off);
        if (lane >= off) s += t;
    }
    if (lane == 31) wsum[wid] = s;
    __syncthreads();
    if (wid == 0) {
        float ws = (lane < 16) ? wsum[lane] : 0.f;
        #pragma unroll
        for (int off = 1; off < 16; off <<= 1) {
            float t = __shfl_up_sync(FULL, ws, off);
            if (lane >= off) ws += t;
        }
        if (lane < 16) wsum[lane] = ws;    // inclusive warp-sum prefix
    }
    __syncthreads();
    float base = (wid == 0) ? 0.f : wsum[wid - 1];
    float inc  = base + s;                  // inclusive prefix at tid
    Cs[tid] = inc;
    float SQ = wsum[15];                    // total sum of Q
    __syncthreads();

    // ---- binary search: m = #{Qs < -P}
    float key = -P;
    int lo = 0, hi = N;
    #pragma unroll
    for (int it = 0; it < 9; it++) {
        int mid = (lo + hi) >> 1;
        bool lt = Qs[mid] < key;
        lo = lt ? mid + 1 : lo;
        hi = lt ? hi : mid;
    }
    float Cm = (lo == 0) ? 0.f : Cs[lo - 1];
    float T  = (float)(N - 2 * lo) * P + SQ - 2.f * Cm;

    float S = 0.55f * ((float)(N - 1) * P + SQ - Q)
            + 0.45f * (T - fabsf(P + Q));
    g_S[(b * N + tid) * HP + k] = S;
}

// ---------------------------------------------------------------------------
// kB: epilogue.  Warp per (b,i) row: par[o] = sum_k S[row][k]*W2[k][o];
// then final combine + softplus.
// ---------------------------------------------------------------------------
__global__ __launch_bounds__(256) void kB(
    const float* __restrict__ inp, const float* __restrict__ W2,
    const float* __restrict__ b2, float* __restrict__ out)
{
    int w    = threadIdx.x >> 5;
    int lane = threadIdx.x & 31;
    int row  = blockIdx.x * 8 + w;          // b*N + i

    const float* Sr = g_S + row * HP;

    float par[OUTF];
    #pragma unroll
    for (int o = 0; o < OUTF; o++) par[o] = 0.f;

    #pragma unroll
    for (int cc = 0; cc < 4; cc++) {
        int kc = lane + 32 * cc;
        if (kc < HID) {
            float s = Sr[kc];
            #pragma unroll
            for (int o = 0; o < OUTF; o++)
                par[o] += s * W2[kc * OUTF + o];
        }
    }
    #pragma unroll
    for (int off = 16; off > 0; off >>= 1)
        #pragma unroll
        for (int o = 0; o < OUTF; o++)
            par[o] += __shfl_down_sync(FULL, par[o], off);

    if (lane == 0) {
        const float* e = inp + row * 6;
        float* ot = out + row * 6;
        float p0 = par[0] + (float)(N - 1) * b2[0];
        float p1 = par[1] + (float)(N - 1) * b2[1];
        float p2 = par[2] + (float)(N - 1) * b2[2];
        float p3 = par[3] + (float)(N - 1) * b2[3];
        float p4 = par[4] + (float)(N - 1) * b2[4];
        float p5 = par[5] + (float)(N - 1) * b2[5];
        ot[0] = e[0] + 0.1f * p0;
        ot[1] = e[1] + 0.1f * p1;
        ot[2] = e[2] + 0.1f * p2;
        ot[3] = e[3] + 0.1f * p3;
        ot[4] = 0.1f * softplus_f(p4);
        ot[5] = 0.1f * softplus_f(p5);
    }
}

// ---------------------------------------------------------------------------
extern "C" void kernel_launch(void* const* d_in, const int* in_sizes, int n_in,
                              void* d_out, int out_size)
{
    const float* inp = (const float*)d_in[0];
    const float* W1  = (const float*)d_in[1];
    const float* b1  = (const float*)d_in[2];
    const float* W2  = (const float*)d_in[3];
    const float* b2  = (const float*)d_in[4];
    float* out = (float*)d_out;

    kA<<<B * HID, 512>>>(inp, W1, b1);
    kB<<<B * N / 8, 256>>>(inp, W2, b2, out);
}